// round 16
// baseline (speedup 1.0000x reference)
#include <cuda_runtime.h>
#include <cuda_fp16.h>
#include <cstdint>

// ---------------------------------------------------------------------------
// Problem constants
// ---------------------------------------------------------------------------
#define BATCH 2
#define SEQ   2048
#define DMODEL 4096
#define NHEADS 32
#define NKV    8
#define HEADD  128
#define GRP    4
#define PAST   1024
#define TTOT   3072
#define NTOK   (BATCH * SEQ)   // 4096
#define KDIM   DMODEL

// ---------------------------------------------------------------------------
// Scratch buffers (device globals; fp16 2-pass scheme)
// ---------------------------------------------------------------------------
__device__ __half g_xh [(size_t)NTOK * DMODEL];
__device__ __half g_qh [(size_t)NTOK * DMODEL];
__device__ __half g_ath[(size_t)NTOK * DMODEL];
__device__ __half g_kch[(size_t)BATCH * NKV * TTOT * HEADD];
__device__ __half g_kcl[(size_t)BATCH * NKV * TTOT * HEADD];
__device__ __half g_vch[(size_t)BATCH * NKV * TTOT * HEADD];
__device__ __half g_vcl[(size_t)BATCH * NKV * TTOT * HEADD];
__device__ __half g_wqt_h[(size_t)DMODEL * KDIM];
__device__ __half g_wqt_l[(size_t)DMODEL * KDIM];
__device__ __half g_wkt_h[(size_t)(NKV*HEADD) * KDIM];
__device__ __half g_wkt_l[(size_t)(NKV*HEADD) * KDIM];
__device__ __half g_wvt_h[(size_t)(NKV*HEADD) * KDIM];
__device__ __half g_wvt_l[(size_t)(NKV*HEADD) * KDIM];
__device__ __half g_wot_h[(size_t)DMODEL * KDIM];
__device__ __half g_wot_l[(size_t)DMODEL * KDIM];

// ---------------------------------------------------------------------------
// PTX helpers
// ---------------------------------------------------------------------------
__device__ __forceinline__ uint32_t smem_to_u32(const void* p) {
    uint32_t a;
    asm("{ .reg .u64 t; cvta.to.shared.u64 t, %1; cvt.u32.u64 %0, t; }"
        : "=r"(a) : "l"(p));
    return a;
}
#define CP_ASYNC16(dst, src) \
    asm volatile("cp.async.ca.shared.global [%0], [%1], 16;" \
        :: "r"(dst), "l"(src))
#define CP_COMMIT() asm volatile("cp.async.commit_group;")
#define CP_WAIT1()  asm volatile("cp.async.wait_group 1;")
#define CP_WAIT0()  asm volatile("cp.async.wait_group 0;")

#define LDMATRIX_X4(r0, r1, r2, r3, addr) \
    asm volatile("ldmatrix.sync.aligned.m8n8.x4.shared.b16 {%0,%1,%2,%3}, [%4];" \
        : "=r"(r0), "=r"(r1), "=r"(r2), "=r"(r3) : "r"(addr))
#define LDMATRIX_X4_T(r0, r1, r2, r3, addr) \
    asm volatile("ldmatrix.sync.aligned.m8n8.x4.trans.shared.b16 {%0,%1,%2,%3}, [%4];" \
        : "=r"(r0), "=r"(r1), "=r"(r2), "=r"(r3) : "r"(addr))

__device__ __forceinline__ void mma_fp16(float* c, const uint32_t* a,
                                         const uint32_t* b) {
    asm volatile(
        "mma.sync.aligned.m16n8k16.row.col.f32.f16.f16.f32 "
        "{%0,%1,%2,%3}, {%4,%5,%6,%7}, {%8,%9}, {%0,%1,%2,%3};"
        : "+f"(c[0]), "+f"(c[1]), "+f"(c[2]), "+f"(c[3])
        : "r"(a[0]), "r"(a[1]), "r"(a[2]), "r"(a[3]), "r"(b[0]), "r"(b[1]));
}

__device__ __forceinline__ uint32_t pack_h2(float a, float b) {
    __half2 h = __floats2half2_rn(a, b);
    return *(uint32_t*)&h;
}
__device__ __forceinline__ void hsplit_store2(
    __half* __restrict__ hi, __half* __restrict__ lo,
    size_t off, float a, float b) {
    __half2 h = __floats2half2_rn(a, b);
    float r0 = a - __low2float(h);
    float r1 = b - __high2float(h);
    __half2 l = __floats2half2_rn(r0, r1);
    *(__half2*)(hi + off) = h;
    *(__half2*)(lo + off) = l;
}

// ---------------------------------------------------------------------------
// fp32 -> fp16 convert (x at entry)
// ---------------------------------------------------------------------------
__global__ __launch_bounds__(256) void conv_kernel(
    const float* __restrict__ src, __half* __restrict__ dst, size_t n)
{
    size_t i = ((size_t)blockIdx.x * 256 + threadIdx.x) * 4;
    if (i >= n) return;
    float4 v = *(const float4*)(src + i);
    *(__half2*)(dst + i)     = __floats2half2_rn(v.x, v.y);
    *(__half2*)(dst + i + 2) = __floats2half2_rn(v.z, v.w);
}

// ---------------------------------------------------------------------------
// Transpose + fp16 split: W[K][N] fp32 -> Wt hi/lo [N][K]
// ---------------------------------------------------------------------------
__global__ __launch_bounds__(256) void tsplit_kernel(
    const float* __restrict__ W, __half* __restrict__ thi,
    __half* __restrict__ tlo, int Kd, int Nd)
{
    __shared__ float t[32][33];
    int tx = threadIdx.x & 31;
    int ty = threadIdx.x >> 5;
    int n_base = blockIdx.x * 32;
    int k_base = blockIdx.y * 32;
#pragma unroll
    for (int j = 0; j < 32; j += 8)
        t[ty + j][tx] = W[(size_t)(k_base + ty + j) * Nd + n_base + tx];
    __syncthreads();
#pragma unroll
    for (int j = 0; j < 32; j += 8) {
        int n = n_base + ty + j;
        int k = k_base + tx;
        float v = t[tx][ty + j];
        __half h = __float2half_rn(v);
        thi[(size_t)n * Kd + k] = h;
        tlo[(size_t)n * Kd + k] = __float2half_rn(v - __half2float(h));
    }
}

// ---------------------------------------------------------------------------
// past_k/past_v [B][P][KV][HD] fp32 -> cache [B][KV][t][HD] fp16 hi/lo
// ---------------------------------------------------------------------------
__global__ __launch_bounds__(256) void past_split_kernel(
    const float* __restrict__ pk, const float* __restrict__ pv)
{
    size_t idx = ((size_t)blockIdx.x * 256 + threadIdx.x) * 4;
    int d  = (int)(idx & 127);
    int kv = (int)((idx >> 7) & 7);
    int p  = (int)((idx >> 10) & 1023);
    int b  = (int)(idx >> 20);
    size_t dst = (((size_t)b * NKV + kv) * TTOT + p) * HEADD + d;
    float4 a = *(const float4*)(pk + idx);
    hsplit_store2(g_kch, g_kcl, dst,     a.x, a.y);
    hsplit_store2(g_kch, g_kcl, dst + 2, a.z, a.w);
    float4 c = *(const float4*)(pv + idx);
    hsplit_store2(g_vch, g_vcl, dst,     c.x, c.y);
    hsplit_store2(g_vch, g_vcl, dst + 2, c.z, c.w);
}

// ---------------------------------------------------------------------------
// fp16 2-pass HMMA GEMM (R14-proven): C = A * (Bh + Bl)^T.
// 128x128 CTA tile, warp 32x64, BK=32, 3-stage cp.async + single barrier,
// 2 CTAs/SM.
//   MODE 0: C fp32 row-major   MODE 1: C fp16 row-major
//   MODE 2: C fp16 hi/lo into KV cache; blockIdx.z: 0=K, 1=V
// ---------------------------------------------------------------------------
#define BK       32
#define ASTRIDE  40
#define TILE_B   (128 * ASTRIDE * 2)      // 10,240 B
#define STAGE_B  (3 * TILE_B)             // 30,720 B (A, Bh, Bl)
#define GSMEM_B  (3 * STAGE_B)            // 92,160 B (x2 CTAs = 184,320)
#define NCHUNK   (KDIM / BK)              // 128

__device__ __forceinline__ void gemm_load_stage(
    uint32_t smem_u, int stage, int kc, int tid,
    const __half* const* srcs)
{
#pragma unroll
    for (int t = 0; t < 3; t++) {
        uint32_t dbase = smem_u + stage * STAGE_B + t * TILE_B;
        const __half* sb = srcs[t] + kc * BK;
#pragma unroll
        for (int i = 0; i < 2; i++) {
            int slot = tid + i * 256;
            int r = slot >> 2;
            int c = slot & 3;
            CP_ASYNC16(dbase + (uint32_t)(r * ASTRIDE + c * 8) * 2,
                       sb + (size_t)r * KDIM + c * 8);
        }
    }
    CP_COMMIT();
}

template<int MODE>
__global__ __launch_bounds__(256, 2) void hmma_gemm_kernel(
    const __half* __restrict__ A,
    const __half* __restrict__ Bh,  const __half* __restrict__ Bl,
    const __half* __restrict__ Bh2, const __half* __restrict__ Bl2,
    float* __restrict__ C, __half* __restrict__ Ch,
    __half* __restrict__ Chi2, __half* __restrict__ Clo2,
    __half* __restrict__ Chi3, __half* __restrict__ Clo3,
    int Ntot)
{
    extern __shared__ char smem[];
    const uint32_t smem_u = smem_to_u32(smem);
    const int tid  = threadIdx.x;
    const int lane = tid & 31;
    const int wid  = tid >> 5;
    const int wm   = (wid >> 1) * 32;
    const int wn   = (wid & 1) * 64;
    const int m0   = blockIdx.y * 128;
    const int n0   = blockIdx.x * 128;

    const __half* bh = Bh;
    const __half* bl = Bl;
    __half* ch_hi = Chi2;
    __half* ch_lo = Clo2;
    if (MODE == 2 && blockIdx.z == 1) {
        bh = Bh2; bl = Bl2; ch_hi = Chi3; ch_lo = Clo3;
    }

    const __half* srcs[3] = {
        A + (size_t)m0 * KDIM,
        bh + (size_t)n0 * KDIM, bl + (size_t)n0 * KDIM };

    float acc[2][8][4];
#pragma unroll
    for (int mt = 0; mt < 2; mt++)
#pragma unroll
        for (int nt = 0; nt < 8; nt++)
#pragma unroll
            for (int r = 0; r < 4; r++) acc[mt][nt][r] = 0.f;

    const int mat  = lane >> 3;
    const int mrow = ((mat & 1) << 3) + (lane & 7);
    const int kadd = (mat >> 1) << 3;

    gemm_load_stage(smem_u, 0, 0, tid, srcs);
    gemm_load_stage(smem_u, 1, 1, tid, srcs);

    for (int kc = 0; kc < NCHUNK; kc++) {
        if (kc == NCHUNK - 1) { CP_WAIT0(); } else { CP_WAIT1(); }
        __syncthreads();

        const int s = kc % 3;
        const uint32_t aB = smem_u + s * STAGE_B;
        const uint32_t bB = aB + TILE_B;

#pragma unroll
        for (int ks = 0; ks < 2; ks++) {
            uint32_t af[2][4];
#pragma unroll
            for (int mt = 0; mt < 2; mt++) {
                uint32_t ad = aB +
                    (uint32_t)((wm + mt * 16 + mrow) * ASTRIDE + ks * 16 + kadd) * 2;
                LDMATRIX_X4(af[mt][0], af[mt][1], af[mt][2], af[mt][3], ad);
            }
#pragma unroll
            for (int nt2 = 0; nt2 < 4; nt2++) {
                uint32_t bd = bB +
                    (uint32_t)((wn + nt2 * 16 + mrow) * ASTRIDE + ks * 16 + kadd) * 2;
                uint32_t r0, r1, r2, r3, e0, e1, e2, e3;
                LDMATRIX_X4(r0, r1, r2, r3, bd);
                LDMATRIX_X4(e0, e1, e2, e3, bd + TILE_B);
                uint32_t bh0[2] = {r0, r2}, bh1[2] = {r1, r3};
                uint32_t bl0[2] = {e0, e2}, bl1[2] = {e1, e3};
#pragma unroll
                for (int mt = 0; mt < 2; mt++) {
                    mma_fp16(acc[mt][2 * nt2],     af[mt], bh0);
                    mma_fp16(acc[mt][2 * nt2],     af[mt], bl0);
                    mma_fp16(acc[mt][2 * nt2 + 1], af[mt], bh1);
                    mma_fp16(acc[mt][2 * nt2 + 1], af[mt], bl1);
                }
            }
        }
        if (kc + 2 < NCHUNK)
            gemm_load_stage(smem_u, (kc + 2) % 3, kc + 2, tid, srcs);
    }

    const int gid = lane >> 2;
    const int tig = lane & 3;
#pragma unroll
    for (int mt = 0; mt < 2; mt++)
#pragma unroll
        for (int nt = 0; nt < 8; nt++) {
            int row = m0 + wm + mt * 16 + gid;
            int col = n0 + wn + nt * 8 + tig * 2;
            if (MODE == 0) {
                *(float2*)&C[(size_t)row * Ntot + col] =
                    make_float2(acc[mt][nt][0], acc[mt][nt][1]);
                *(float2*)&C[(size_t)(row + 8) * Ntot + col] =
                    make_float2(acc[mt][nt][2], acc[mt][nt][3]);
            } else if (MODE == 1) {
                *(__half2*)&Ch[(size_t)row * Ntot + col] =
                    __floats2half2_rn(acc[mt][nt][0], acc[mt][nt][1]);
                *(__half2*)&Ch[(size_t)(row + 8) * Ntot + col] =
                    __floats2half2_rn(acc[mt][nt][2], acc[mt][nt][3]);
            } else {
                int kvh = col >> 7, d = col & 127;
#pragma unroll
                for (int rr = 0; rr < 2; rr++) {
                    int r = row + rr * 8;
                    int bb = r >> 11, ss = r & 2047;
                    size_t off = (((size_t)bb * NKV + kvh) * TTOT + PAST + ss)
                                 * HEADD + d;
                    hsplit_store2(ch_hi, ch_lo, off,
                                  acc[mt][nt][rr * 2], acc[mt][nt][rr * 2 + 1]);
                }
            }
        }
}

// ---------------------------------------------------------------------------
// fp16 2-pass flash attention, BM=256 (halves KV L2 traffic vs BM=128).
// 8 warps x 32 query rows (2 m16 blocks each), BN=64, V frags shared
// across both m-blocks in PV phase.
// ---------------------------------------------------------------------------
#define FA_BM   256
#define FA_BN   64
#define FA_STR  136
#define FA_QTILE (FA_BM * FA_STR * 2)       // 69,632 B
#define FA_KTILE (FA_BN * FA_STR * 2)       // 17,408 B
#define FA_STAGE (4 * FA_KTILE)             // 69,632 B
#define FA_KV_OFF FA_QTILE
#define FA_SMEM  (FA_KV_OFF + 2 * FA_STAGE) // 208,896 B

__global__ __launch_bounds__(256, 1) void fa_kernel(
    const __half* __restrict__ qh, __half* __restrict__ ath)
{
    extern __shared__ char smem[];
    const uint32_t su = smem_to_u32(smem);
    const int tid = threadIdx.x, lane = tid & 31, wid = tid >> 5;
    const int q0 = blockIdx.x * FA_BM;
    const int h = blockIdx.y, b = blockIdx.z, kvh = h >> 2;

    const size_t kvbase = ((size_t)b * NKV + kvh) * TTOT * HEADD;
    const __half* kH = g_kch + kvbase;
    const __half* kL = g_kcl + kvbase;
    const __half* vH = g_vch + kvbase;
    const __half* vL = g_vcl + kvbase;

    {
        const size_t qoff = (size_t)(b * SEQ + q0) * DMODEL + h * HEADD;
        const __half* sh = qh + qoff;
#pragma unroll
        for (int i = 0; i < 16; i++) {
            int slot = tid + i * 256;          // 0..4095
            int r = slot >> 4, c = slot & 15;
            CP_ASYNC16(su + (uint32_t)(r * FA_STR + c * 8) * 2,
                       sh + (size_t)r * DMODEL + c * 8);
        }
    }
    auto load_kv = [&](int stage, int t) {
        uint32_t base = su + FA_KV_OFF + stage * FA_STAGE;
        int n0 = t * FA_BN;
#pragma unroll
        for (int i = 0; i < 4; i++) {
            int slot = tid + i * 256;
            int r = slot >> 4, c = slot & 15;
            uint32_t doff = (uint32_t)(r * FA_STR + c * 8) * 2;
            size_t soff = (size_t)(n0 + r) * HEADD + c * 8;
            CP_ASYNC16(base + doff,                kH + soff);
            CP_ASYNC16(base + FA_KTILE + doff,     kL + soff);
            CP_ASYNC16(base + 2 * FA_KTILE + doff, vH + soff);
            CP_ASYNC16(base + 3 * FA_KTILE + doff, vL + soff);
        }
    };
    const int ntiles = (PAST + q0 + FA_BM) / FA_BN;
    load_kv(0, 0); CP_COMMIT();
    load_kv(1, 1); CP_COMMIT();

    const int gid = lane >> 2, tig = lane & 3;
    const int mat = lane >> 3;
    const int mrow = ((mat & 1) << 3) + (lane & 7);
    const int kadd = (mat >> 1) << 3;
    const int wm = wid * 32;                   // 32 query rows per warp
    // causal limits: [mt][half]
    int lim[2][2];
#pragma unroll
    for (int mt = 0; mt < 2; mt++) {
        lim[mt][0] = PAST + q0 + wm + mt * 16 + gid;
        lim[mt][1] = lim[mt][0] + 8;
    }

    float mrun[2][2], lrun[2][2];
#pragma unroll
    for (int mt = 0; mt < 2; mt++)
#pragma unroll
        for (int hf = 0; hf < 2; hf++) { mrun[mt][hf] = -1e30f; lrun[mt][hf] = 0.f; }

    float oacc[2][16][4];
#pragma unroll
    for (int mt = 0; mt < 2; mt++)
#pragma unroll
        for (int i = 0; i < 16; i++)
#pragma unroll
            for (int r = 0; r < 4; r++) oacc[mt][i][r] = 0.f;

    const int vrow = ((mat & 1) << 3) + (lane & 7);

    for (int t = 0; t < ntiles; t++) {
        if (t == ntiles - 1) { CP_WAIT0(); } else { CP_WAIT1(); }
        __syncthreads();
        const uint32_t sk = su + FA_KV_OFF + (t & 1) * FA_STAGE;
        const int n0 = t * FA_BN;

        float sacc[2][8][4];
#pragma unroll
        for (int mt = 0; mt < 2; mt++)
#pragma unroll
            for (int j = 0; j < 8; j++)
#pragma unroll
                for (int r = 0; r < 4; r++) sacc[mt][j][r] = 0.f;

#pragma unroll
        for (int ks = 0; ks < 8; ks++) {
            uint32_t ah[2][4];
#pragma unroll
            for (int mt = 0; mt < 2; mt++) {
                uint32_t ad = su +
                    (uint32_t)((wm + mt * 16 + mrow) * FA_STR + ks * 16 + kadd) * 2;
                LDMATRIX_X4(ah[mt][0], ah[mt][1], ah[mt][2], ah[mt][3], ad);
            }
#pragma unroll
            for (int nt2 = 0; nt2 < 4; nt2++) {
                uint32_t bd = sk +
                    (uint32_t)((nt2 * 16 + mrow) * FA_STR + ks * 16 + kadd) * 2;
                uint32_t h0, h1, h2, h3, e0, e1, e2, e3;
                LDMATRIX_X4(h0, h1, h2, h3, bd);
                LDMATRIX_X4(e0, e1, e2, e3, bd + FA_KTILE);
                uint32_t bh0[2] = {h0, h2}, bh1[2] = {h1, h3};
                uint32_t bl0[2] = {e0, e2}, bl1[2] = {e1, e3};
#pragma unroll
                for (int mt = 0; mt < 2; mt++) {
                    mma_fp16(sacc[mt][2 * nt2],     ah[mt], bh0);
                    mma_fp16(sacc[mt][2 * nt2],     ah[mt], bl0);
                    mma_fp16(sacc[mt][2 * nt2 + 1], ah[mt], bh1);
                    mma_fp16(sacc[mt][2 * nt2 + 1], ah[mt], bl1);
                }
            }
        }

        const float sc = 0.088388347648318447f;
#pragma unroll
        for (int mt = 0; mt < 2; mt++) {
            float tm0 = -1e30f, tm1 = -1e30f;
#pragma unroll
            for (int j = 0; j < 8; j++) {
                int c0 = n0 + j * 8 + tig * 2;
                float s0 = sacc[mt][j][0] * sc; if (c0     > lim[mt][0]) s0 = -1e30f;
                float s1 = sacc[mt][j][1] * sc; if (c0 + 1 > lim[mt][0]) s1 = -1e30f;
                float s2 = sacc[mt][j][2] * sc; if (c0     > lim[mt][1]) s2 = -1e30f;
                float s3 = sacc[mt][j][3] * sc; if (c0 + 1 > lim[mt][1]) s3 = -1e30f;
                sacc[mt][j][0] = s0; sacc[mt][j][1] = s1;
                sacc[mt][j][2] = s2; sacc[mt][j][3] = s3;
                tm0 = fmaxf(tm0, fmaxf(s0, s1));
                tm1 = fmaxf(tm1, fmaxf(s2, s3));
            }
            tm0 = fmaxf(tm0, __shfl_xor_sync(0xffffffffu, tm0, 1));
            tm0 = fmaxf(tm0, __shfl_xor_sync(0xffffffffu, tm0, 2));
            tm1 = fmaxf(tm1, __shfl_xor_sync(0xffffffffu, tm1, 1));
            tm1 = fmaxf(tm1, __shfl_xor_sync(0xffffffffu, tm1, 2));

            float mn0 = fmaxf(mrun[mt][0], tm0);
            float mn1 = fmaxf(mrun[mt][1], tm1);
            float al0 = __expf(mrun[mt][0] - mn0);
            float al1 = __expf(mrun[mt][1] - mn1);
            mrun[mt][0] = mn0; mrun[mt][1] = mn1;
#pragma unroll
            for (int i = 0; i < 16; i++) {
                oacc[mt][i][0] *= al0; oacc[mt][i][1] *= al0;
                oacc[mt][i][2] *= al1; oacc[mt][i][3] *= al1;
            }
            float rs0 = 0.f, rs1 = 0.f;
#pragma unroll
            for (int j = 0; j < 8; j++) {
                float p0 = __expf(sacc[mt][j][0] - mn0);
                float p1 = __expf(sacc[mt][j][1] - mn0);
                float p2 = __expf(sacc[mt][j][2] - mn1);
                float p3 = __expf(sacc[mt][j][3] - mn1);
                sacc[mt][j][0] = p0; sacc[mt][j][1] = p1;
                sacc[mt][j][2] = p2; sacc[mt][j][3] = p3;
                rs0 += p0 + p1; rs1 += p2 + p3;
            }
            rs0 += __shfl_xor_sync(0xffffffffu, rs0, 1);
            rs0 += __shfl_xor_sync(0xffffffffu, rs0, 2);
            rs1 += __shfl_xor_sync(0xffffffffu, rs1, 1);
            rs1 += __shfl_xor_sync(0xffffffffu, rs1, 2);
            lrun[mt][0] = lrun[mt][0] * al0 + rs0;
            lrun[mt][1] = lrun[mt][1] * al1 + rs1;
        }

        // ---- PV: V fragments shared across both m-blocks ----
#pragma unroll
        for (int tk = 0; tk < 4; tk++) {
            uint32_t ph[2][4];
#pragma unroll
            for (int mt = 0; mt < 2; mt++) {
                ph[mt][0] = pack_h2(sacc[mt][2 * tk][0],     sacc[mt][2 * tk][1]);
                ph[mt][1] = pack_h2(sacc[mt][2 * tk][2],     sacc[mt][2 * tk][3]);
                ph[mt][2] = pack_h2(sacc[mt][2 * tk + 1][0], sacc[mt][2 * tk + 1][1]);
                ph[mt][3] = pack_h2(sacc[mt][2 * tk + 1][2], sacc[mt][2 * tk + 1][3]);
            }
#pragma unroll
            for (int dt2 = 0; dt2 < 8; dt2++) {
                uint32_t vd = sk + 2 * FA_KTILE +
                    (uint32_t)((tk * 16 + vrow) * FA_STR + dt2 * 16 + kadd) * 2;
                uint32_t r0, r1, r2, r3, s0, s1, s2, s3;
                LDMATRIX_X4_T(r0, r1, r2, r3, vd);
                LDMATRIX_X4_T(s0, s1, s2, s3, vd + FA_KTILE);
                uint32_t bh0[2] = {r0, r1}, bh1[2] = {r2, r3};
                uint32_t bl0[2] = {s0, s1}, bl1[2] = {s2, s3};
#pragma unroll
                for (int mt = 0; mt < 2; mt++) {
                    mma_fp16(oacc[mt][2 * dt2],     ph[mt], bh0);
                    mma_fp16(oacc[mt][2 * dt2],     ph[mt], bl0);
                    mma_fp16(oacc[mt][2 * dt2 + 1], ph[mt], bh1);
                    mma_fp16(oacc[mt][2 * dt2 + 1], ph[mt], bl1);
                }
            }
        }
        __syncthreads();
        if (t + 2 < ntiles) { load_kv(t & 1, t + 2); }
    }

    // ---- epilogue ----
#pragma unroll
    for (int mt = 0; mt < 2; mt++) {
        float inv0 = 1.f / lrun[mt][0], inv1 = 1.f / lrun[mt][1];
        size_t tok0 = (size_t)(b * SEQ + q0 + wm + mt * 16 + gid);
        size_t base0 = tok0 * DMODEL + h * HEADD;
        size_t base1 = base0 + (size_t)8 * DMODEL;
#pragma unroll
        for (int i = 0; i < 16; i++) {
            int d0 = i * 8 + tig * 2;
            *(__half2*)&ath[base0 + d0] =
                __floats2half2_rn(oacc[mt][i][0] * inv0, oacc[mt][i][1] * inv0);
            *(__half2*)&ath[base1 + d0] =
                __floats2half2_rn(oacc[mt][i][2] * inv1, oacc[mt][i][3] * inv1);
        }
    }
}

// ---------------------------------------------------------------------------
// Launch
// ---------------------------------------------------------------------------
extern "C" void kernel_launch(void* const* d_in, const int* in_sizes, int n_in,
                              void* d_out, int out_size)
{
    const float* x      = (const float*)d_in[0];
    const float* past_k = (const float*)d_in[1];
    const float* past_v = (const float*)d_in[2];
    const float* Wq     = (const float*)d_in[3];
    const float* Wk     = (const float*)d_in[4];
    const float* Wv     = (const float*)d_in[5];
    const float* Wo     = (const float*)d_in[6];
    float* out = (float*)d_out;

    void *pxh, *pqh, *path;
    void *pkch, *pkcl, *pvch, *pvcl;
    void *pwqh, *pwql, *pwkh, *pwkl, *pwvh, *pwvl, *pwoh, *pwol;
    cudaGetSymbolAddress(&pxh, g_xh);
    cudaGetSymbolAddress(&pqh, g_qh);
    cudaGetSymbolAddress(&path, g_ath);
    cudaGetSymbolAddress(&pkch, g_kch);  cudaGetSymbolAddress(&pkcl, g_kcl);
    cudaGetSymbolAddress(&pvch, g_vch);  cudaGetSymbolAddress(&pvcl, g_vcl);
    cudaGetSymbolAddress(&pwqh, g_wqt_h); cudaGetSymbolAddress(&pwql, g_wqt_l);
    cudaGetSymbolAddress(&pwkh, g_wkt_h); cudaGetSymbolAddress(&pwkl, g_wkt_l);
    cudaGetSymbolAddress(&pwvh, g_wvt_h); cudaGetSymbolAddress(&pwvl, g_wvt_l);
    cudaGetSymbolAddress(&pwoh, g_wot_h); cudaGetSymbolAddress(&pwol, g_wot_l);

    cudaFuncSetAttribute(hmma_gemm_kernel<0>,
        cudaFuncAttributeMaxDynamicSharedMemorySize, (int)GSMEM_B);
    cudaFuncSetAttribute(hmma_gemm_kernel<1>,
        cudaFuncAttributeMaxDynamicSharedMemorySize, (int)GSMEM_B);
    cudaFuncSetAttribute(hmma_gemm_kernel<2>,
        cudaFuncAttributeMaxDynamicSharedMemorySize, (int)GSMEM_B);
    cudaFuncSetAttribute(fa_kernel,
        cudaFuncAttributeMaxDynamicSharedMemorySize, (int)FA_SMEM);

    const size_t nx = (size_t)NTOK * DMODEL;
    dim3 blk(256);

    // ---- conversions ----
    conv_kernel<<<(unsigned)(nx / (256 * 4)), blk>>>(x, (__half*)pxh, nx);
    tsplit_kernel<<<dim3(DMODEL / 32, KDIM / 32), blk>>>(
        Wq, (__half*)pwqh, (__half*)pwql, KDIM, DMODEL);
    tsplit_kernel<<<dim3((NKV * HEADD) / 32, KDIM / 32), blk>>>(
        Wk, (__half*)pwkh, (__half*)pwkl, KDIM, NKV * HEADD);
    tsplit_kernel<<<dim3((NKV * HEADD) / 32, KDIM / 32), blk>>>(
        Wv, (__half*)pwvh, (__half*)pwvl, KDIM, NKV * HEADD);
    tsplit_kernel<<<dim3(DMODEL / 32, KDIM / 32), blk>>>(
        Wo, (__half*)pwoh, (__half*)pwol, KDIM, DMODEL);
    past_split_kernel<<<2048, blk>>>(past_k, past_v);

    // ---- Q projection (single fp16 out) ----
    hmma_gemm_kernel<1><<<dim3(DMODEL / 128, NTOK / 128), blk, GSMEM_B>>>(
        (const __half*)pxh,
        (const __half*)pwqh, (const __half*)pwql, nullptr, nullptr,
        nullptr, (__half*)pqh, nullptr, nullptr, nullptr, nullptr, DMODEL);
    // ---- fused K+V projection (blockIdx.z: 0=K, 1=V) ----
    hmma_gemm_kernel<2><<<dim3((NKV * HEADD) / 128, NTOK / 128, 2), blk, GSMEM_B>>>(
        (const __half*)pxh,
        (const __half*)pwkh, (const __half*)pwkl,
        (const __half*)pwvh, (const __half*)pwvl,
        nullptr, nullptr,
        (__half*)pkch, (__half*)pkcl, (__half*)pvch, (__half*)pvcl,
        NKV * HEADD);

    // ---- flash attention (fp16 2-pass, BM=256) ----
    fa_kernel<<<dim3(SEQ / FA_BM, NHEADS, BATCH), blk, FA_SMEM>>>(
        (const __half*)pqh, (__half*)path);

    // ---- O projection -> d_out (fp32 out) ----
    hmma_gemm_kernel<0><<<dim3(DMODEL / 128, NTOK / 128), blk, GSMEM_B>>>(
        (const __half*)path,
        (const __half*)pwoh, (const __half*)pwol, nullptr, nullptr,
        out, nullptr, nullptr, nullptr, nullptr, nullptr, DMODEL);
}

// round 17
// speedup vs baseline: 1.5860x; 1.5860x over previous
#include <cuda_runtime.h>
#include <cuda_fp16.h>
#include <cstdint>

// ---------------------------------------------------------------------------
// Problem constants
// ---------------------------------------------------------------------------
#define BATCH 2
#define SEQ   2048
#define DMODEL 4096
#define NHEADS 32
#define NKV    8
#define HEADD  128
#define GRP    4
#define PAST   1024
#define TTOT   3072
#define NTOK   (BATCH * SEQ)   // 4096
#define KDIM   DMODEL

// ---------------------------------------------------------------------------
// Scratch buffers (device globals; fp16 2-pass scheme:
//   A-side operands single fp16; B-side operands hi/lo fp16)
// ---------------------------------------------------------------------------
__device__ __half g_xh [(size_t)NTOK * DMODEL];
__device__ __half g_qh [(size_t)NTOK * DMODEL];
__device__ __half g_ath[(size_t)NTOK * DMODEL];
__device__ __half g_kch[(size_t)BATCH * NKV * TTOT * HEADD];
__device__ __half g_kcl[(size_t)BATCH * NKV * TTOT * HEADD];
__device__ __half g_vch[(size_t)BATCH * NKV * TTOT * HEADD];
__device__ __half g_vcl[(size_t)BATCH * NKV * TTOT * HEADD];
__device__ __half g_wqt_h[(size_t)DMODEL * KDIM];
__device__ __half g_wqt_l[(size_t)DMODEL * KDIM];
__device__ __half g_wkt_h[(size_t)(NKV*HEADD) * KDIM];
__device__ __half g_wkt_l[(size_t)(NKV*HEADD) * KDIM];
__device__ __half g_wvt_h[(size_t)(NKV*HEADD) * KDIM];
__device__ __half g_wvt_l[(size_t)(NKV*HEADD) * KDIM];
__device__ __half g_wot_h[(size_t)DMODEL * KDIM];
__device__ __half g_wot_l[(size_t)DMODEL * KDIM];

// ---------------------------------------------------------------------------
// PTX helpers
// ---------------------------------------------------------------------------
__device__ __forceinline__ uint32_t smem_to_u32(const void* p) {
    uint32_t a;
    asm("{ .reg .u64 t; cvta.to.shared.u64 t, %1; cvt.u32.u64 %0, t; }"
        : "=r"(a) : "l"(p));
    return a;
}
#define CP_ASYNC16(dst, src) \
    asm volatile("cp.async.ca.shared.global [%0], [%1], 16;" \
        :: "r"(dst), "l"(src))
#define CP_COMMIT() asm volatile("cp.async.commit_group;")
#define CP_WAIT1()  asm volatile("cp.async.wait_group 1;")
#define CP_WAIT0()  asm volatile("cp.async.wait_group 0;")

#define LDMATRIX_X4(r0, r1, r2, r3, addr) \
    asm volatile("ldmatrix.sync.aligned.m8n8.x4.shared.b16 {%0,%1,%2,%3}, [%4];" \
        : "=r"(r0), "=r"(r1), "=r"(r2), "=r"(r3) : "r"(addr))
#define LDMATRIX_X4_T(r0, r1, r2, r3, addr) \
    asm volatile("ldmatrix.sync.aligned.m8n8.x4.trans.shared.b16 {%0,%1,%2,%3}, [%4];" \
        : "=r"(r0), "=r"(r1), "=r"(r2), "=r"(r3) : "r"(addr))

__device__ __forceinline__ void mma_fp16(float* c, const uint32_t* a,
                                         const uint32_t* b) {
    asm volatile(
        "mma.sync.aligned.m16n8k16.row.col.f32.f16.f16.f32 "
        "{%0,%1,%2,%3}, {%4,%5,%6,%7}, {%8,%9}, {%0,%1,%2,%3};"
        : "+f"(c[0]), "+f"(c[1]), "+f"(c[2]), "+f"(c[3])
        : "r"(a[0]), "r"(a[1]), "r"(a[2]), "r"(a[3]), "r"(b[0]), "r"(b[1]));
}

__device__ __forceinline__ uint32_t pack_h2(float a, float b) {
    __half2 h = __floats2half2_rn(a, b);
    return *(uint32_t*)&h;
}
__device__ __forceinline__ void hsplit_store2(
    __half* __restrict__ hi, __half* __restrict__ lo,
    size_t off, float a, float b) {
    __half2 h = __floats2half2_rn(a, b);
    float r0 = a - __low2float(h);
    float r1 = b - __high2float(h);
    __half2 l = __floats2half2_rn(r0, r1);
    *(__half2*)(hi + off) = h;
    *(__half2*)(lo + off) = l;
}

// ---------------------------------------------------------------------------
// fp32 -> fp16 convert (x at entry)
// ---------------------------------------------------------------------------
__global__ __launch_bounds__(256) void conv_kernel(
    const float* __restrict__ src, __half* __restrict__ dst, size_t n)
{
    size_t i = ((size_t)blockIdx.x * 256 + threadIdx.x) * 4;
    if (i >= n) return;
    float4 v = *(const float4*)(src + i);
    *(__half2*)(dst + i)     = __floats2half2_rn(v.x, v.y);
    *(__half2*)(dst + i + 2) = __floats2half2_rn(v.z, v.w);
}

// ---------------------------------------------------------------------------
// Transpose + fp16 split: W[K][N] fp32 -> Wt hi/lo [N][K]
// ---------------------------------------------------------------------------
__global__ __launch_bounds__(256) void tsplit_kernel(
    const float* __restrict__ W, __half* __restrict__ thi,
    __half* __restrict__ tlo, int Kd, int Nd)
{
    __shared__ float t[32][33];
    int tx = threadIdx.x & 31;
    int ty = threadIdx.x >> 5;
    int n_base = blockIdx.x * 32;
    int k_base = blockIdx.y * 32;
#pragma unroll
    for (int j = 0; j < 32; j += 8)
        t[ty + j][tx] = W[(size_t)(k_base + ty + j) * Nd + n_base + tx];
    __syncthreads();
#pragma unroll
    for (int j = 0; j < 32; j += 8) {
        int n = n_base + ty + j;
        int k = k_base + tx;
        float v = t[tx][ty + j];
        __half h = __float2half_rn(v);
        thi[(size_t)n * Kd + k] = h;
        tlo[(size_t)n * Kd + k] = __float2half_rn(v - __half2float(h));
    }
}

// ---------------------------------------------------------------------------
// past_k/past_v [B][P][KV][HD] fp32 -> cache [B][KV][t][HD] fp16 hi/lo
// ---------------------------------------------------------------------------
__global__ __launch_bounds__(256) void past_split_kernel(
    const float* __restrict__ pk, const float* __restrict__ pv)
{
    size_t idx = ((size_t)blockIdx.x * 256 + threadIdx.x) * 4;
    int d  = (int)(idx & 127);
    int kv = (int)((idx >> 7) & 7);
    int p  = (int)((idx >> 10) & 1023);
    int b  = (int)(idx >> 20);
    size_t dst = (((size_t)b * NKV + kv) * TTOT + p) * HEADD + d;
    float4 a = *(const float4*)(pk + idx);
    hsplit_store2(g_kch, g_kcl, dst,     a.x, a.y);
    hsplit_store2(g_kch, g_kcl, dst + 2, a.z, a.w);
    float4 c = *(const float4*)(pv + idx);
    hsplit_store2(g_vch, g_vcl, dst,     c.x, c.y);
    hsplit_store2(g_vch, g_vcl, dst + 2, c.z, c.w);
}

// ---------------------------------------------------------------------------
// fp16 2-pass HMMA GEMM (R14-proven): C = A * (Bh + Bl)^T.
// 128x128 CTA tile, warp 32x64, BK=32, 3-stage cp.async + single barrier,
// 2 CTAs/SM.
//   MODE 0: C fp32 row-major   MODE 1: C fp16 row-major
//   MODE 2: C fp16 hi/lo into KV cache; blockIdx.z: 0=K, 1=V
// ---------------------------------------------------------------------------
#define BK       32
#define ASTRIDE  40
#define TILE_B   (128 * ASTRIDE * 2)      // 10,240 B
#define STAGE_B  (3 * TILE_B)             // 30,720 B (A, Bh, Bl)
#define GSMEM_B  (3 * STAGE_B)            // 92,160 B (x2 CTAs = 184,320)
#define NCHUNK   (KDIM / BK)              // 128

__device__ __forceinline__ void gemm_load_stage(
    uint32_t smem_u, int stage, int kc, int tid,
    const __half* const* srcs)
{
#pragma unroll
    for (int t = 0; t < 3; t++) {
        uint32_t dbase = smem_u + stage * STAGE_B + t * TILE_B;
        const __half* sb = srcs[t] + kc * BK;
#pragma unroll
        for (int i = 0; i < 2; i++) {
            int slot = tid + i * 256;
            int r = slot >> 2;
            int c = slot & 3;
            CP_ASYNC16(dbase + (uint32_t)(r * ASTRIDE + c * 8) * 2,
                       sb + (size_t)r * KDIM + c * 8);
        }
    }
    CP_COMMIT();
}

template<int MODE>
__global__ __launch_bounds__(256, 2) void hmma_gemm_kernel(
    const __half* __restrict__ A,
    const __half* __restrict__ Bh,  const __half* __restrict__ Bl,
    const __half* __restrict__ Bh2, const __half* __restrict__ Bl2,
    float* __restrict__ C, __half* __restrict__ Ch,
    __half* __restrict__ Chi2, __half* __restrict__ Clo2,
    __half* __restrict__ Chi3, __half* __restrict__ Clo3,
    int Ntot)
{
    extern __shared__ char smem[];
    const uint32_t smem_u = smem_to_u32(smem);
    const int tid  = threadIdx.x;
    const int lane = tid & 31;
    const int wid  = tid >> 5;
    const int wm   = (wid >> 1) * 32;
    const int wn   = (wid & 1) * 64;
    const int m0   = blockIdx.y * 128;
    const int n0   = blockIdx.x * 128;

    const __half* bh = Bh;
    const __half* bl = Bl;
    __half* ch_hi = Chi2;
    __half* ch_lo = Clo2;
    if (MODE == 2 && blockIdx.z == 1) {
        bh = Bh2; bl = Bl2; ch_hi = Chi3; ch_lo = Clo3;
    }

    const __half* srcs[3] = {
        A + (size_t)m0 * KDIM,
        bh + (size_t)n0 * KDIM, bl + (size_t)n0 * KDIM };

    float acc[2][8][4];
#pragma unroll
    for (int mt = 0; mt < 2; mt++)
#pragma unroll
        for (int nt = 0; nt < 8; nt++)
#pragma unroll
            for (int r = 0; r < 4; r++) acc[mt][nt][r] = 0.f;

    const int mat  = lane >> 3;
    const int mrow = ((mat & 1) << 3) + (lane & 7);
    const int kadd = (mat >> 1) << 3;

    gemm_load_stage(smem_u, 0, 0, tid, srcs);
    gemm_load_stage(smem_u, 1, 1, tid, srcs);

    for (int kc = 0; kc < NCHUNK; kc++) {
        if (kc == NCHUNK - 1) { CP_WAIT0(); } else { CP_WAIT1(); }
        __syncthreads();    // orders cp.async data; also frees stage (kc+2)%3

        const int s = kc % 3;
        const uint32_t aB = smem_u + s * STAGE_B;
        const uint32_t bB = aB + TILE_B;

#pragma unroll
        for (int ks = 0; ks < 2; ks++) {
            uint32_t af[2][4];
#pragma unroll
            for (int mt = 0; mt < 2; mt++) {
                uint32_t ad = aB +
                    (uint32_t)((wm + mt * 16 + mrow) * ASTRIDE + ks * 16 + kadd) * 2;
                LDMATRIX_X4(af[mt][0], af[mt][1], af[mt][2], af[mt][3], ad);
            }
#pragma unroll
            for (int nt2 = 0; nt2 < 4; nt2++) {
                uint32_t bd = bB +
                    (uint32_t)((wn + nt2 * 16 + mrow) * ASTRIDE + ks * 16 + kadd) * 2;
                uint32_t r0, r1, r2, r3, e0, e1, e2, e3;
                LDMATRIX_X4(r0, r1, r2, r3, bd);
                LDMATRIX_X4(e0, e1, e2, e3, bd + TILE_B);
                uint32_t bh0[2] = {r0, r2}, bh1[2] = {r1, r3};
                uint32_t bl0[2] = {e0, e2}, bl1[2] = {e1, e3};
#pragma unroll
                for (int mt = 0; mt < 2; mt++) {
                    mma_fp16(acc[mt][2 * nt2],     af[mt], bh0);
                    mma_fp16(acc[mt][2 * nt2],     af[mt], bl0);
                    mma_fp16(acc[mt][2 * nt2 + 1], af[mt], bh1);
                    mma_fp16(acc[mt][2 * nt2 + 1], af[mt], bl1);
                }
            }
        }
        if (kc + 2 < NCHUNK)
            gemm_load_stage(smem_u, (kc + 2) % 3, kc + 2, tid, srcs);
    }

    const int gid = lane >> 2;
    const int tig = lane & 3;
#pragma unroll
    for (int mt = 0; mt < 2; mt++)
#pragma unroll
        for (int nt = 0; nt < 8; nt++) {
            int row = m0 + wm + mt * 16 + gid;
            int col = n0 + wn + nt * 8 + tig * 2;
            if (MODE == 0) {
                *(float2*)&C[(size_t)row * Ntot + col] =
                    make_float2(acc[mt][nt][0], acc[mt][nt][1]);
                *(float2*)&C[(size_t)(row + 8) * Ntot + col] =
                    make_float2(acc[mt][nt][2], acc[mt][nt][3]);
            } else if (MODE == 1) {
                *(__half2*)&Ch[(size_t)row * Ntot + col] =
                    __floats2half2_rn(acc[mt][nt][0], acc[mt][nt][1]);
                *(__half2*)&Ch[(size_t)(row + 8) * Ntot + col] =
                    __floats2half2_rn(acc[mt][nt][2], acc[mt][nt][3]);
            } else {
                int kvh = col >> 7, d = col & 127;
#pragma unroll
                for (int rr = 0; rr < 2; rr++) {
                    int r = row + rr * 8;
                    int bb = r >> 11, ss = r & 2047;
                    size_t off = (((size_t)bb * NKV + kvh) * TTOT + PAST + ss)
                                 * HEADD + d;
                    hsplit_store2(ch_hi, ch_lo, off,
                                  acc[mt][nt][rr * 2], acc[mt][nt][rr * 2 + 1]);
                }
            }
        }
}

// ---------------------------------------------------------------------------
// fp16 2-pass flash attention (R14-proven, BM=128) + LPT heavy-first order.
// ---------------------------------------------------------------------------
#define FA_BM   128
#define FA_BN   64
#define FA_STR  136
#define FA_QTILE (FA_BM * FA_STR * 2)       // 34,816 B
#define FA_KTILE (FA_BN * FA_STR * 2)       // 17,408 B
#define FA_STAGE (4 * FA_KTILE)             // 69,632 B
#define FA_KV_OFF FA_QTILE
#define FA_SMEM  (FA_KV_OFF + 2 * FA_STAGE) // 174,080 B

__global__ __launch_bounds__(256, 1) void fa_kernel(
    const __half* __restrict__ qh, __half* __restrict__ ath)
{
    extern __shared__ char smem[];
    const uint32_t su = smem_to_u32(smem);
    const int tid = threadIdx.x, lane = tid & 31, wid = tid >> 5;
    // LPT: heaviest q-tiles (most KV iterations) scheduled first
    const int q0 = (gridDim.x - 1 - blockIdx.x) * FA_BM;
    const int h = blockIdx.y, b = blockIdx.z, kvh = h >> 2;

    const size_t kvbase = ((size_t)b * NKV + kvh) * TTOT * HEADD;
    const __half* kH = g_kch + kvbase;
    const __half* kL = g_kcl + kvbase;
    const __half* vH = g_vch + kvbase;
    const __half* vL = g_vcl + kvbase;

    {
        const size_t qoff = (size_t)(b * SEQ + q0) * DMODEL + h * HEADD;
        const __half* sh = qh + qoff;
#pragma unroll
        for (int i = 0; i < 8; i++) {
            int slot = tid + i * 256;
            int r = slot >> 4, c = slot & 15;
            CP_ASYNC16(su + (uint32_t)(r * FA_STR + c * 8) * 2,
                       sh + (size_t)r * DMODEL + c * 8);
        }
    }
    auto load_kv = [&](int stage, int t) {
        uint32_t base = su + FA_KV_OFF + stage * FA_STAGE;
        int n0 = t * FA_BN;
#pragma unroll
        for (int i = 0; i < 4; i++) {
            int slot = tid + i * 256;
            int r = slot >> 4, c = slot & 15;
            uint32_t doff = (uint32_t)(r * FA_STR + c * 8) * 2;
            size_t soff = (size_t)(n0 + r) * HEADD + c * 8;
            CP_ASYNC16(base + doff,                kH + soff);
            CP_ASYNC16(base + FA_KTILE + doff,     kL + soff);
            CP_ASYNC16(base + 2 * FA_KTILE + doff, vH + soff);
            CP_ASYNC16(base + 3 * FA_KTILE + doff, vL + soff);
        }
    };
    const int ntiles = (PAST + q0 + FA_BM) / FA_BN;
    load_kv(0, 0); CP_COMMIT();
    load_kv(1, 1); CP_COMMIT();

    const int gid = lane >> 2, tig = lane & 3;
    const int mat = lane >> 3;
    const int mrow = ((mat & 1) << 3) + (lane & 7);
    const int kadd = (mat >> 1) << 3;
    const int wm = wid * 16;
    const int lim0 = PAST + q0 + wm + gid;
    const int lim1 = lim0 + 8;

    float m0 = -1e30f, m1 = -1e30f, l0 = 0.f, l1 = 0.f;
    float oacc[16][4];
#pragma unroll
    for (int i = 0; i < 16; i++)
#pragma unroll
        for (int r = 0; r < 4; r++) oacc[i][r] = 0.f;

    const int vrow = ((mat & 1) << 3) + (lane & 7);

    for (int t = 0; t < ntiles; t++) {
        if (t == ntiles - 1) { CP_WAIT0(); } else { CP_WAIT1(); }
        __syncthreads();
        const uint32_t sk = su + FA_KV_OFF + (t & 1) * FA_STAGE;
        const int n0 = t * FA_BN;

        float sacc[8][4];
#pragma unroll
        for (int j = 0; j < 8; j++)
#pragma unroll
            for (int r = 0; r < 4; r++) sacc[j][r] = 0.f;

#pragma unroll
        for (int ks = 0; ks < 8; ks++) {
            uint32_t ah[4];
            uint32_t ad = su + (uint32_t)((wm + mrow) * FA_STR + ks * 16 + kadd) * 2;
            LDMATRIX_X4(ah[0], ah[1], ah[2], ah[3], ad);
#pragma unroll
            for (int nt2 = 0; nt2 < 4; nt2++) {
                uint32_t bd = sk +
                    (uint32_t)((nt2 * 16 + mrow) * FA_STR + ks * 16 + kadd) * 2;
                uint32_t h0, h1, h2, h3, e0, e1, e2, e3;
                LDMATRIX_X4(h0, h1, h2, h3, bd);
                LDMATRIX_X4(e0, e1, e2, e3, bd + FA_KTILE);
                uint32_t bh0[2] = {h0, h2}, bh1[2] = {h1, h3};
                uint32_t bl0[2] = {e0, e2}, bl1[2] = {e1, e3};
                mma_fp16(sacc[2 * nt2],     ah, bh0);
                mma_fp16(sacc[2 * nt2],     ah, bl0);
                mma_fp16(sacc[2 * nt2 + 1], ah, bh1);
                mma_fp16(sacc[2 * nt2 + 1], ah, bl1);
            }
        }

        const float sc = 0.088388347648318447f;
        float tm0 = -1e30f, tm1 = -1e30f;
#pragma unroll
        for (int j = 0; j < 8; j++) {
            int c0 = n0 + j * 8 + tig * 2;
            float s0 = sacc[j][0] * sc; if (c0     > lim0) s0 = -1e30f;
            float s1 = sacc[j][1] * sc; if (c0 + 1 > lim0) s1 = -1e30f;
            float s2 = sacc[j][2] * sc; if (c0     > lim1) s2 = -1e30f;
            float s3 = sacc[j][3] * sc; if (c0 + 1 > lim1) s3 = -1e30f;
            sacc[j][0] = s0; sacc[j][1] = s1; sacc[j][2] = s2; sacc[j][3] = s3;
            tm0 = fmaxf(tm0, fmaxf(s0, s1));
            tm1 = fmaxf(tm1, fmaxf(s2, s3));
        }
        tm0 = fmaxf(tm0, __shfl_xor_sync(0xffffffffu, tm0, 1));
        tm0 = fmaxf(tm0, __shfl_xor_sync(0xffffffffu, tm0, 2));
        tm1 = fmaxf(tm1, __shfl_xor_sync(0xffffffffu, tm1, 1));
        tm1 = fmaxf(tm1, __shfl_xor_sync(0xffffffffu, tm1, 2));

        float mn0 = fmaxf(m0, tm0), mn1 = fmaxf(m1, tm1);
        float al0 = __expf(m0 - mn0), al1 = __expf(m1 - mn1);
        m0 = mn0; m1 = mn1;
#pragma unroll
        for (int i = 0; i < 16; i++) {
            oacc[i][0] *= al0; oacc[i][1] *= al0;
            oacc[i][2] *= al1; oacc[i][3] *= al1;
        }

        float rs0 = 0.f, rs1 = 0.f;
#pragma unroll
        for (int j = 0; j < 8; j++) {
            float p0 = __expf(sacc[j][0] - mn0);
            float p1 = __expf(sacc[j][1] - mn0);
            float p2 = __expf(sacc[j][2] - mn1);
            float p3 = __expf(sacc[j][3] - mn1);
            sacc[j][0] = p0; sacc[j][1] = p1; sacc[j][2] = p2; sacc[j][3] = p3;
            rs0 += p0 + p1; rs1 += p2 + p3;
        }
        rs0 += __shfl_xor_sync(0xffffffffu, rs0, 1);
        rs0 += __shfl_xor_sync(0xffffffffu, rs0, 2);
        rs1 += __shfl_xor_sync(0xffffffffu, rs1, 1);
        rs1 += __shfl_xor_sync(0xffffffffu, rs1, 2);
        l0 = l0 * al0 + rs0;
        l1 = l1 * al1 + rs1;

#pragma unroll
        for (int tk = 0; tk < 4; tk++) {
            uint32_t ph[4];
            ph[0] = pack_h2(sacc[2 * tk][0],     sacc[2 * tk][1]);
            ph[1] = pack_h2(sacc[2 * tk][2],     sacc[2 * tk][3]);
            ph[2] = pack_h2(sacc[2 * tk + 1][0], sacc[2 * tk + 1][1]);
            ph[3] = pack_h2(sacc[2 * tk + 1][2], sacc[2 * tk + 1][3]);
#pragma unroll
            for (int dt2 = 0; dt2 < 8; dt2++) {
                uint32_t vd = sk + 2 * FA_KTILE +
                    (uint32_t)((tk * 16 + vrow) * FA_STR + dt2 * 16 + kadd) * 2;
                uint32_t r0, r1, r2, r3, s0, s1, s2, s3;
                LDMATRIX_X4_T(r0, r1, r2, r3, vd);
                LDMATRIX_X4_T(s0, s1, s2, s3, vd + FA_KTILE);
                uint32_t bh0[2] = {r0, r1}, bh1[2] = {r2, r3};
                uint32_t bl0[2] = {s0, s1}, bl1[2] = {s2, s3};
                mma_fp16(oacc[2 * dt2],     ph, bh0);
                mma_fp16(oacc[2 * dt2],     ph, bl0);
                mma_fp16(oacc[2 * dt2 + 1], ph, bh1);
                mma_fp16(oacc[2 * dt2 + 1], ph, bl1);
            }
        }
        __syncthreads();
        if (t + 2 < ntiles) { load_kv(t & 1, t + 2); }
    }

    float inv0 = 1.f / l0, inv1 = 1.f / l1;
    size_t tok0 = (size_t)(b * SEQ + q0 + wm + gid);
    size_t base0 = tok0 * DMODEL + h * HEADD;
    size_t base1 = base0 + (size_t)8 * DMODEL;
#pragma unroll
    for (int i = 0; i < 16; i++) {
        int d0 = i * 8 + tig * 2;
        *(__half2*)&ath[base0 + d0] =
            __floats2half2_rn(oacc[i][0] * inv0, oacc[i][1] * inv0);
        *(__half2*)&ath[base1 + d0] =
            __floats2half2_rn(oacc[i][2] * inv1, oacc[i][3] * inv1);
    }
}

// ---------------------------------------------------------------------------
// Launch
// ---------------------------------------------------------------------------
extern "C" void kernel_launch(void* const* d_in, const int* in_sizes, int n_in,
                              void* d_out, int out_size)
{
    const float* x      = (const float*)d_in[0];
    const float* past_k = (const float*)d_in[1];
    const float* past_v = (const float*)d_in[2];
    const float* Wq     = (const float*)d_in[3];
    const float* Wk     = (const float*)d_in[4];
    const float* Wv     = (const float*)d_in[5];
    const float* Wo     = (const float*)d_in[6];
    float* out = (float*)d_out;

    void *pxh, *pqh, *path;
    void *pkch, *pkcl, *pvch, *pvcl;
    void *pwqh, *pwql, *pwkh, *pwkl, *pwvh, *pwvl, *pwoh, *pwol;
    cudaGetSymbolAddress(&pxh, g_xh);
    cudaGetSymbolAddress(&pqh, g_qh);
    cudaGetSymbolAddress(&path, g_ath);
    cudaGetSymbolAddress(&pkch, g_kch);  cudaGetSymbolAddress(&pkcl, g_kcl);
    cudaGetSymbolAddress(&pvch, g_vch);  cudaGetSymbolAddress(&pvcl, g_vcl);
    cudaGetSymbolAddress(&pwqh, g_wqt_h); cudaGetSymbolAddress(&pwql, g_wqt_l);
    cudaGetSymbolAddress(&pwkh, g_wkt_h); cudaGetSymbolAddress(&pwkl, g_wkt_l);
    cudaGetSymbolAddress(&pwvh, g_wvt_h); cudaGetSymbolAddress(&pwvl, g_wvt_l);
    cudaGetSymbolAddress(&pwoh, g_wot_h); cudaGetSymbolAddress(&pwol, g_wot_l);

    cudaFuncSetAttribute(hmma_gemm_kernel<0>,
        cudaFuncAttributeMaxDynamicSharedMemorySize, (int)GSMEM_B);
    cudaFuncSetAttribute(hmma_gemm_kernel<1>,
        cudaFuncAttributeMaxDynamicSharedMemorySize, (int)GSMEM_B);
    cudaFuncSetAttribute(hmma_gemm_kernel<2>,
        cudaFuncAttributeMaxDynamicSharedMemorySize, (int)GSMEM_B);
    cudaFuncSetAttribute(fa_kernel,
        cudaFuncAttributeMaxDynamicSharedMemorySize, (int)FA_SMEM);

    const size_t nx = (size_t)NTOK * DMODEL;
    dim3 blk(256);

    // ---- conversions ----
    conv_kernel<<<(unsigned)(nx / (256 * 4)), blk>>>(x, (__half*)pxh, nx);
    tsplit_kernel<<<dim3(DMODEL / 32, KDIM / 32), blk>>>(
        Wq, (__half*)pwqh, (__half*)pwql, KDIM, DMODEL);
    tsplit_kernel<<<dim3((NKV * HEADD) / 32, KDIM / 32), blk>>>(
        Wk, (__half*)pwkh, (__half*)pwkl, KDIM, NKV * HEADD);
    tsplit_kernel<<<dim3((NKV * HEADD) / 32, KDIM / 32), blk>>>(
        Wv, (__half*)pwvh, (__half*)pwvl, KDIM, NKV * HEADD);
    tsplit_kernel<<<dim3(DMODEL / 32, KDIM / 32), blk>>>(
        Wo, (__half*)pwoh, (__half*)pwol, KDIM, DMODEL);
    past_split_kernel<<<2048, blk>>>(past_k, past_v);

    // ---- Q projection (single fp16 out) ----
    hmma_gemm_kernel<1><<<dim3(DMODEL / 128, NTOK / 128), blk, GSMEM_B>>>(
        (const __half*)pxh,
        (const __half*)pwqh, (const __half*)pwql, nullptr, nullptr,
        nullptr, (__half*)pqh, nullptr, nullptr, nullptr, nullptr, DMODEL);
    // ---- fused K+V projection (blockIdx.z: 0=K, 1=V) ----
    hmma_gemm_kernel<2><<<dim3((NKV * HEADD) / 128, NTOK / 128, 2), blk, GSMEM_B>>>(
        (const __half*)pxh,
        (const __half*)pwkh, (const __half*)pwkl,
        (const __half*)pwvh, (const __half*)pwvl,
        nullptr, nullptr,
        (__half*)pkch, (__half*)pkcl, (__half*)pvch, (__half*)pvcl,
        NKV * HEADD);

    // ---- flash attention (fp16 2-pass, LPT order) ----
    fa_kernel<<<dim3(SEQ / FA_BM, NHEADS, BATCH), blk, FA_SMEM>>>(
        (const __half*)pqh, (__half*)path);

    // ---- O projection -> d_out (fp32 out) ----
    hmma_gemm_kernel<0><<<dim3(DMODEL / 128, NTOK / 128), blk, GSMEM_B>>>(
        (const __half*)path,
        (const __half*)pwoh, (const __half*)pwol, nullptr, nullptr,
        out, nullptr, nullptr, nullptr, nullptr, nullptr, DMODEL);
}